// round 1
// baseline (speedup 1.0000x reference)
#include <cuda_runtime.h>

#define NN 50000
#define EE 800000

// ---------------- scratch (device globals; no allocation allowed) ----------
__device__ float g_SQa[NN * 2];
__device__ float g_SKa[NN * 2];
__device__ float g_SQb[NN * 2];
__device__ float g_SKb[NN * 2];
__device__ float g_vpa[NN * 64];
__device__ float g_vpb[NN * 64];
__device__ float g_sa[NN * 2];
__device__ float g_sb[NN * 2];
__device__ float g_agga[NN * 64];
__device__ float g_aggb[NN * 64];

__device__ __forceinline__ float tanh_fast(float x) {
    // tanh via exp; clamp avoids inf/inf. Accuracy ~1e-6 rel.
    x = fminf(15.0f, fmaxf(-15.0f, x));
    float e = __expf(2.0f * x);
    return __fdividef(e - 1.0f, e + 1.0f);
}

// ---------------- zero scratch each call (graph replays reuse it) ----------
__global__ void zero_all_kernel() {
    int i = blockIdx.x * blockDim.x + threadIdx.x;
    float4 z = make_float4(0.f, 0.f, 0.f, 0.f);
    if (i < NN * 64 / 4) {
        reinterpret_cast<float4*>(g_agga)[i] = z;
        reinterpret_cast<float4*>(g_aggb)[i] = z;
    }
    if (i < NN * 2 / 4) {
        reinterpret_cast<float4*>(g_sa)[i] = z;
        reinterpret_cast<float4*>(g_sb)[i] = z;
    }
}

// ---------------- projection: per node compute SQ, SK scalars + vp row -----
// q = x@Wq, k = x@Wk, v = x@Wv
// SQ[n,h] = sum_o tanh(q[h,o]+emb[h,o]) * a[o]
// SK[n,h] = sum_o tanh(k[h,o]+emb[h,o]) * a[32+o]
// vp[n,j] = v[n,j] + rel[j]
__global__ void __launch_bounds__(128) proj_kernel(
    const float* __restrict__ x,
    const float* __restrict__ Wq, const float* __restrict__ Wk,
    const float* __restrict__ Wv,
    const float* __restrict__ emb, const float* __restrict__ rel,
    const float* __restrict__ a_attn,
    float* __restrict__ SQ, float* __restrict__ SK, float* __restrict__ vp)
{
    __shared__ float sW[3 * 64 * 64];  // Wq | Wk | Wv, exactly 48KB
    int tid = threadIdx.x;
    for (int i = tid; i < 4096; i += 128) {
        sW[i]        = Wq[i];
        sW[4096 + i] = Wk[i];
        sW[8192 + i] = Wv[i];
    }
    __syncthreads();

    int node = blockIdx.x * 128 + tid;
    if (node >= NN) return;

    float4 xr[16];
    const float4* xp = reinterpret_cast<const float4*>(x + node * 64);
#pragma unroll
    for (int i = 0; i < 16; i++) xr[i] = __ldg(xp + i);

    float sq0 = 0.f, sq1 = 0.f, sk0 = 0.f, sk1 = 0.f;
    float* vpo = vp + node * 64;

#pragma unroll 1
    for (int jc = 0; jc < 16; jc++) {
        int j4 = jc * 4;
        float4 q4 = make_float4(0.f, 0.f, 0.f, 0.f);
        float4 k4 = make_float4(0.f, 0.f, 0.f, 0.f);
        float4 v4 = make_float4(0.f, 0.f, 0.f, 0.f);
#pragma unroll
        for (int kk4 = 0; kk4 < 16; kk4++) {
            float4 xv = xr[kk4];
#pragma unroll
            for (int c = 0; c < 4; c++) {
                float xs = (c == 0) ? xv.x : (c == 1) ? xv.y : (c == 2) ? xv.z : xv.w;
                int kk = kk4 * 4 + c;
                float4 wq4 = *reinterpret_cast<const float4*>(sW + kk * 64 + j4);
                float4 wk4 = *reinterpret_cast<const float4*>(sW + 4096 + kk * 64 + j4);
                float4 wv4 = *reinterpret_cast<const float4*>(sW + 8192 + kk * 64 + j4);
                q4.x = fmaf(xs, wq4.x, q4.x); q4.y = fmaf(xs, wq4.y, q4.y);
                q4.z = fmaf(xs, wq4.z, q4.z); q4.w = fmaf(xs, wq4.w, q4.w);
                k4.x = fmaf(xs, wk4.x, k4.x); k4.y = fmaf(xs, wk4.y, k4.y);
                k4.z = fmaf(xs, wk4.z, k4.z); k4.w = fmaf(xs, wk4.w, k4.w);
                v4.x = fmaf(xs, wv4.x, v4.x); v4.y = fmaf(xs, wv4.y, v4.y);
                v4.z = fmaf(xs, wv4.z, v4.z); v4.w = fmaf(xs, wv4.w, v4.w);
            }
        }
        // epilogue for the 4 channels j4..j4+3
        float qv[4] = {q4.x, q4.y, q4.z, q4.w};
        float kv[4] = {k4.x, k4.y, k4.z, k4.w};
        float vv[4] = {v4.x, v4.y, v4.z, v4.w};
        float4 vout;
        float* vo = reinterpret_cast<float*>(&vout);
#pragma unroll
        for (int c = 0; c < 4; c++) {
            int j = j4 + c;
            int o = j & 31;
            float ej = __ldg(emb + j);
            float rj = __ldg(rel + j);
            float aq = __ldg(a_attn + o);
            float ak = __ldg(a_attn + 32 + o);
            float tq = tanh_fast(qv[c] + ej);
            float tk = tanh_fast(kv[c] + ej);
            if (jc < 8) { sq0 = fmaf(tq, aq, sq0); sk0 = fmaf(tk, ak, sk0); }
            else        { sq1 = fmaf(tq, aq, sq1); sk1 = fmaf(tk, ak, sk1); }
            vo[c] = vv[c] + rj;
        }
        *reinterpret_cast<float4*>(vpo + j4) = vout;
    }
    SQ[node * 2]     = sq0;
    SQ[node * 2 + 1] = sq1;
    SK[node * 2]     = sk0;
    SK[node * 2 + 1] = sk1;
}

// ---------------- edge pass: one warp per edge, single fused pass ----------
// lane handles channels (2*lane, 2*lane+1); head h = lane>>4.
// score(e,h) = SQ[col,h] + SK[row,h] + C_rel[h] + sum_o tanh(eb[h,o])*a[96+o]
// agg[col] += (vp[row] + eb) * exp(score);  s[col,h] += exp(score)
__global__ void __launch_bounds__(256) edge_kernel(
    const float* __restrict__ ea,
    const int* __restrict__ row, const int* __restrict__ col,
    const float* __restrict__ a_attn, const float* __restrict__ rel,
    const float* __restrict__ SQd, const float* __restrict__ SKs,
    const float* __restrict__ vps,
    float* __restrict__ s, float* __restrict__ agg,
    const float* __restrict__ We)
{
    int lane = threadIdx.x & 31;
    int gw = (blockIdx.x * blockDim.x + threadIdx.x) >> 5;
    int nw = (gridDim.x * blockDim.x) >> 5;

    // We columns for this lane's two channels
    float2 w2[16];
#pragma unroll
    for (int k = 0; k < 16; k++)
        w2[k] = __ldg(reinterpret_cast<const float2*>(We + k * 64) + lane);

    int o0 = (2 * lane) & 31;
    float aeA = __ldg(a_attn + 96 + o0);
    float aeB = __ldg(a_attn + 96 + o0 + 1);
    int h = lane >> 4;

    // per-head relation constant C_rel[h] (reduced within half-warp)
    float2 r2 = __ldg(reinterpret_cast<const float2*>(rel) + lane);
    float cc = tanh_fast(r2.x) * aeA + tanh_fast(r2.y) * aeB;
    cc += __shfl_xor_sync(0xffffffffu, cc, 8);
    cc += __shfl_xor_sync(0xffffffffu, cc, 4);
    cc += __shfl_xor_sync(0xffffffffu, cc, 2);
    cc += __shfl_xor_sync(0xffffffffu, cc, 1);

    for (int e = gw; e < EE; e += nw) {
        int r = __ldg(row + e);
        int c = __ldg(col + e);

        const float4* eap = reinterpret_cast<const float4*>(ea + (size_t)e * 16);
        float4 A = __ldg(eap), B = __ldg(eap + 1), C4 = __ldg(eap + 2), D = __ldg(eap + 3);
        float eav[16] = {A.x, A.y, A.z, A.w, B.x, B.y, B.z, B.w,
                         C4.x, C4.y, C4.z, C4.w, D.x, D.y, D.z, D.w};

        float ebA = 0.f, ebB = 0.f;
#pragma unroll
        for (int k = 0; k < 16; k++) {
            ebA = fmaf(eav[k], w2[k].x, ebA);
            ebB = fmaf(eav[k], w2[k].y, ebB);
        }

        float se = tanh_fast(ebA) * aeA + tanh_fast(ebB) * aeB;
        se += __shfl_xor_sync(0xffffffffu, se, 8);
        se += __shfl_xor_sync(0xffffffffu, se, 4);
        se += __shfl_xor_sync(0xffffffffu, se, 2);
        se += __shfl_xor_sync(0xffffffffu, se, 1);

        float score = se + __ldg(SQd + 2 * c + h) + __ldg(SKs + 2 * r + h) + cc;
        float ex = __expf(score);

        float2 v2 = __ldg(reinterpret_cast<const float2*>(vps + r * 64) + lane);
        float vA = (v2.x + ebA) * ex;
        float vB = (v2.y + ebB) * ex;

        float* dst = agg + c * 64 + 2 * lane;
        atomicAdd(dst, vA);
        atomicAdd(dst + 1, vB);
        if (o0 == 0) atomicAdd(s + 2 * c + h, ex);  // lanes 0 and 16
    }
}

// ---------------- epilogue: fin = (agg/s)@Wo + bo + x@Wr -------------------
__global__ void __launch_bounds__(128) final_kernel(
    const float* __restrict__ agg, const float* __restrict__ s,
    const float* __restrict__ x,
    const float* __restrict__ Wo, const float* __restrict__ bo,
    const float* __restrict__ Wr,
    float* __restrict__ out)
{
    __shared__ float sWo[64 * 32];
    __shared__ float sWr[64 * 32];
    __shared__ float sbo[32];
    int tid = threadIdx.x;
    for (int i = tid; i < 2048; i += 128) { sWo[i] = Wo[i]; sWr[i] = Wr[i]; }
    if (tid < 32) sbo[tid] = bo[tid];
    __syncthreads();

    int node = blockIdx.x * 128 + tid;
    if (node >= NN) return;

    float s0 = __ldg(s + node * 2);
    float s1 = __ldg(s + node * 2 + 1);
    float i0 = (s0 != 0.f) ? __fdividef(1.f, s0) : 0.f;
    float i1 = (s1 != 0.f) ? __fdividef(1.f, s1) : 0.f;

    float an[64], xr[64];
    const float4* ap = reinterpret_cast<const float4*>(agg + node * 64);
    const float4* xp = reinterpret_cast<const float4*>(x + node * 64);
#pragma unroll
    for (int i = 0; i < 16; i++) {
        float inv = (i < 8) ? i0 : i1;
        float4 a4 = __ldg(ap + i);
        an[i * 4 + 0] = a4.x * inv; an[i * 4 + 1] = a4.y * inv;
        an[i * 4 + 2] = a4.z * inv; an[i * 4 + 3] = a4.w * inv;
        float4 x4 = __ldg(xp + i);
        xr[i * 4 + 0] = x4.x; xr[i * 4 + 1] = x4.y;
        xr[i * 4 + 2] = x4.z; xr[i * 4 + 3] = x4.w;
    }

    float* op = out + node * 32;
#pragma unroll 1
    for (int jc = 0; jc < 8; jc++) {
        int j4 = jc * 4;
        float4 acc = *reinterpret_cast<const float4*>(sbo + j4);
#pragma unroll
        for (int kk = 0; kk < 64; kk++) {
            float4 wo4 = *reinterpret_cast<const float4*>(sWo + kk * 32 + j4);
            float4 wr4 = *reinterpret_cast<const float4*>(sWr + kk * 32 + j4);
            float av = an[kk], xv = xr[kk];
            acc.x = fmaf(av, wo4.x, acc.x); acc.y = fmaf(av, wo4.y, acc.y);
            acc.z = fmaf(av, wo4.z, acc.z); acc.w = fmaf(av, wo4.w, acc.w);
            acc.x = fmaf(xv, wr4.x, acc.x); acc.y = fmaf(xv, wr4.y, acc.y);
            acc.z = fmaf(xv, wr4.z, acc.z); acc.w = fmaf(xv, wr4.w, acc.w);
        }
        *reinterpret_cast<float4*>(op + j4) = acc;
    }
}

// ---------------- launch ---------------------------------------------------
extern "C" void kernel_launch(void* const* d_in, const int* in_sizes, int n_in,
                              void* d_out, int out_size) {
    const float* x_a   = (const float*)d_in[0];
    const float* x_b   = (const float*)d_in[1];
    const float* ea1   = (const float*)d_in[2];
    const float* ea2   = (const float*)d_in[3];
    const float* Wq_a  = (const float*)d_in[4];
    const float* Wk_a  = (const float*)d_in[5];
    const float* Wv_a  = (const float*)d_in[6];
    const float* Wq_b  = (const float*)d_in[7];
    const float* Wk_b  = (const float*)d_in[8];
    const float* Wv_b  = (const float*)d_in[9];
    const float* emb_a = (const float*)d_in[10];
    const float* emb_b = (const float*)d_in[11];
    const float* rel1  = (const float*)d_in[12];
    const float* rel2  = (const float*)d_in[13];
    const float* We    = (const float*)d_in[14];
    const float* a_at  = (const float*)d_in[15];
    const float* Wo_a  = (const float*)d_in[16];
    const float* bo_a  = (const float*)d_in[17];
    const float* Wo_b  = (const float*)d_in[18];
    const float* bo_b  = (const float*)d_in[19];
    const float* Wr_a  = (const float*)d_in[20];
    const float* Wr_b  = (const float*)d_in[21];
    const int*   row1  = (const int*)d_in[22];
    const int*   col1  = (const int*)d_in[23];
    const int*   row2  = (const int*)d_in[24];
    const int*   col2  = (const int*)d_in[25];
    float* out = (float*)d_out;

    void *pSQa, *pSKa, *pSQb, *pSKb, *pvpa, *pvpb, *psa, *psb, *pagga, *paggb;
    cudaGetSymbolAddress(&pSQa, g_SQa);
    cudaGetSymbolAddress(&pSKa, g_SKa);
    cudaGetSymbolAddress(&pSQb, g_SQb);
    cudaGetSymbolAddress(&pSKb, g_SKb);
    cudaGetSymbolAddress(&pvpa, g_vpa);
    cudaGetSymbolAddress(&pvpb, g_vpb);
    cudaGetSymbolAddress(&psa, g_sa);
    cudaGetSymbolAddress(&psb, g_sb);
    cudaGetSymbolAddress(&pagga, g_agga);
    cudaGetSymbolAddress(&paggb, g_aggb);

    zero_all_kernel<<<(NN * 16 + 255) / 256, 256>>>();

    int pblocks = (NN + 127) / 128;
    // type a: src in relation1 (rel1), its emb is emb_a
    proj_kernel<<<pblocks, 128>>>(x_a, Wq_a, Wk_a, Wv_a, emb_a, rel1, a_at,
                                  (float*)pSQa, (float*)pSKa, (float*)pvpa);
    // type b: src in relation2 (rel2), its emb is emb_b
    proj_kernel<<<pblocks, 128>>>(x_b, Wq_b, Wk_b, Wv_b, emb_b, rel2, a_at,
                                  (float*)pSQb, (float*)pSKb, (float*)pvpb);

    // relation1: a -> b  (dst = b)
    edge_kernel<<<2048, 256>>>(ea1, row1, col1, a_at, rel1,
                               (const float*)pSQb, (const float*)pSKa,
                               (const float*)pvpa,
                               (float*)psb, (float*)paggb, We);
    // relation2: b -> a  (dst = a)
    edge_kernel<<<2048, 256>>>(ea2, row2, col2, a_at, rel2,
                               (const float*)pSQa, (const float*)pSKb,
                               (const float*)pvpb,
                               (float*)psa, (float*)pagga, We);

    final_kernel<<<pblocks, 128>>>((const float*)pagga, (const float*)psa,
                                   x_a, Wo_a, bo_a, Wr_a, out);
    final_kernel<<<pblocks, 128>>>((const float*)paggb, (const float*)psb,
                                   x_b, Wo_b, bo_b, Wr_b, out + NN * 32);
}

// round 2
// speedup vs baseline: 1.4258x; 1.4258x over previous
#include <cuda_runtime.h>

#define NN 50000
#define EE 800000

// ---------------- scratch (device globals; no allocation allowed) ----------
__device__ float g_SQa[NN * 2];
__device__ float g_SKa[NN * 2];
__device__ float g_SQb[NN * 2];
__device__ float g_SKb[NN * 2];
__device__ float g_vpa[NN * 64];
__device__ float g_vpb[NN * 64];
__device__ float g_sa[NN * 2];
__device__ float g_sb[NN * 2];
__device__ float g_agga[NN * 64];
__device__ float g_aggb[NN * 64];

__device__ __forceinline__ float tanh_h(float x) {
    float y;
    asm("tanh.approx.f32 %0, %1;" : "=f"(y) : "f"(x));
    return y;
}

__device__ __forceinline__ void red_add_v4(float* p, float4 v) {
    asm volatile("red.global.add.v4.f32 [%0], {%1, %2, %3, %4};"
                 :: "l"(p), "f"(v.x), "f"(v.y), "f"(v.z), "f"(v.w) : "memory");
}

// ---------------- zero scratch each call (graph replays reuse it) ----------
__global__ void zero_all_kernel() {
    int i = blockIdx.x * blockDim.x + threadIdx.x;
    float4 z = make_float4(0.f, 0.f, 0.f, 0.f);
    if (i < NN * 64 / 4) {
        reinterpret_cast<float4*>(g_agga)[i] = z;
        reinterpret_cast<float4*>(g_aggb)[i] = z;
    }
    if (i < NN * 2 / 4) {
        reinterpret_cast<float4*>(g_sa)[i] = z;
        reinterpret_cast<float4*>(g_sb)[i] = z;
    }
}

// ---------------- projection: per node compute SQ, SK scalars + vp row -----
// SQ[n,h] = sum_o tanh(q[h,o]+emb[h,o]) * a[o]
// SK[n,h] = sum_o tanh(k[h,o]+emb[h,o]) * a[32+o]
// vp[n,j] = v[n,j] + rel[j]
// Merged for both node types: blockIdx.x < pb -> type a, else type b.
__global__ void __launch_bounds__(128) proj_kernel(
    const float* __restrict__ x_a,
    const float* __restrict__ Wq_a, const float* __restrict__ Wk_a,
    const float* __restrict__ Wv_a,
    const float* __restrict__ emb_a, const float* __restrict__ rel_a,
    float* __restrict__ SQ_a, float* __restrict__ SK_a, float* __restrict__ vp_a,
    const float* __restrict__ x_b,
    const float* __restrict__ Wq_b, const float* __restrict__ Wk_b,
    const float* __restrict__ Wv_b,
    const float* __restrict__ emb_b, const float* __restrict__ rel_b,
    float* __restrict__ SQ_b, float* __restrict__ SK_b, float* __restrict__ vp_b,
    const float* __restrict__ a_attn, int pb)
{
    int typ = (blockIdx.x >= pb);
    int blk = typ ? (blockIdx.x - pb) : blockIdx.x;
    const float* x   = typ ? x_b   : x_a;
    const float* Wq  = typ ? Wq_b  : Wq_a;
    const float* Wk  = typ ? Wk_b  : Wk_a;
    const float* Wv  = typ ? Wv_b  : Wv_a;
    const float* emb = typ ? emb_b : emb_a;
    const float* rel = typ ? rel_b : rel_a;
    float* SQ = typ ? SQ_b : SQ_a;
    float* SK = typ ? SK_b : SK_a;
    float* vp = typ ? vp_b : vp_a;

    __shared__ float sW[3 * 64 * 64];  // Wq | Wk | Wv, exactly 48KB
    int tid = threadIdx.x;
    for (int i = tid; i < 4096; i += 128) {
        sW[i]        = Wq[i];
        sW[4096 + i] = Wk[i];
        sW[8192 + i] = Wv[i];
    }
    __syncthreads();

    int node = blk * 128 + tid;
    if (node >= NN) return;

    float4 xr[16];
    const float4* xp = reinterpret_cast<const float4*>(x + node * 64);
#pragma unroll
    for (int i = 0; i < 16; i++) xr[i] = __ldg(xp + i);

    float sq0 = 0.f, sq1 = 0.f, sk0 = 0.f, sk1 = 0.f;
    float* vpo = vp + node * 64;

#pragma unroll 1
    for (int jc = 0; jc < 16; jc++) {
        int j4 = jc * 4;
        float4 q4 = make_float4(0.f, 0.f, 0.f, 0.f);
        float4 k4 = make_float4(0.f, 0.f, 0.f, 0.f);
        float4 v4 = make_float4(0.f, 0.f, 0.f, 0.f);
#pragma unroll
        for (int kk4 = 0; kk4 < 16; kk4++) {
            float4 xv = xr[kk4];
#pragma unroll
            for (int c = 0; c < 4; c++) {
                float xs = (c == 0) ? xv.x : (c == 1) ? xv.y : (c == 2) ? xv.z : xv.w;
                int kk = kk4 * 4 + c;
                float4 wq4 = *reinterpret_cast<const float4*>(sW + kk * 64 + j4);
                float4 wk4 = *reinterpret_cast<const float4*>(sW + 4096 + kk * 64 + j4);
                float4 wv4 = *reinterpret_cast<const float4*>(sW + 8192 + kk * 64 + j4);
                q4.x = fmaf(xs, wq4.x, q4.x); q4.y = fmaf(xs, wq4.y, q4.y);
                q4.z = fmaf(xs, wq4.z, q4.z); q4.w = fmaf(xs, wq4.w, q4.w);
                k4.x = fmaf(xs, wk4.x, k4.x); k4.y = fmaf(xs, wk4.y, k4.y);
                k4.z = fmaf(xs, wk4.z, k4.z); k4.w = fmaf(xs, wk4.w, k4.w);
                v4.x = fmaf(xs, wv4.x, v4.x); v4.y = fmaf(xs, wv4.y, v4.y);
                v4.z = fmaf(xs, wv4.z, v4.z); v4.w = fmaf(xs, wv4.w, v4.w);
            }
        }
        float qv[4] = {q4.x, q4.y, q4.z, q4.w};
        float kv[4] = {k4.x, k4.y, k4.z, k4.w};
        float vv[4] = {v4.x, v4.y, v4.z, v4.w};
        float4 vout;
        float* vo = reinterpret_cast<float*>(&vout);
#pragma unroll
        for (int c = 0; c < 4; c++) {
            int j = j4 + c;
            int o = j & 31;
            float ej = __ldg(emb + j);
            float rj = __ldg(rel + j);
            float aq = __ldg(a_attn + o);
            float ak = __ldg(a_attn + 32 + o);
            float tq = tanh_h(qv[c] + ej);
            float tk = tanh_h(kv[c] + ej);
            if (jc < 8) { sq0 = fmaf(tq, aq, sq0); sk0 = fmaf(tk, ak, sk0); }
            else        { sq1 = fmaf(tq, aq, sq1); sk1 = fmaf(tk, ak, sk1); }
            vo[c] = vv[c] + rj;
        }
        *reinterpret_cast<float4*>(vpo + j4) = vout;
    }
    SQ[node * 2]     = sq0;
    SQ[node * 2 + 1] = sq1;
    SK[node * 2]     = sk0;
    SK[node * 2 + 1] = sk1;
}

// ---------------- edge pass: half-warp per edge, 4 channels per lane -------
// lane l in [0,16) handles channels 4l..4l+3; head h = l>>3; sub = lane>>4
// picks which edge of the warp's pair. One red.v4 per lane into agg.
__global__ void __launch_bounds__(256, 5) edge_kernel(
    const float* __restrict__ ea1,
    const int* __restrict__ row1, const int* __restrict__ col1,
    const float* __restrict__ SQ1, const float* __restrict__ SK1,
    const float* __restrict__ vp1,
    float* __restrict__ s1, float* __restrict__ agg1,
    const float* __restrict__ rel1,
    const float* __restrict__ ea2,
    const int* __restrict__ row2, const int* __restrict__ col2,
    const float* __restrict__ SQ2, const float* __restrict__ SK2,
    const float* __restrict__ vp2,
    float* __restrict__ s2, float* __restrict__ agg2,
    const float* __restrict__ rel2,
    const float* __restrict__ a_attn, const float* __restrict__ We)
{
    __shared__ float4 sWe[256];  // We as 16 rows x 16 float4 (64 ch)
    int tid = threadIdx.x;
    sWe[tid] = reinterpret_cast<const float4*>(We)[tid];
    __syncthreads();

    int r_sel = blockIdx.x & 1;
    const float* ea  = r_sel ? ea2  : ea1;
    const int*   row = r_sel ? row2 : row1;
    const int*   col = r_sel ? col2 : col1;
    const float* SQd = r_sel ? SQ2 : SQ1;
    const float* SKs = r_sel ? SK2 : SK1;
    const float* vps = r_sel ? vp2 : vp1;
    float*       s   = r_sel ? s2  : s1;
    float*       agg = r_sel ? agg2 : agg1;
    const float* relv = r_sel ? rel2 : rel1;

    int lane = tid & 31;
    int l = lane & 15;          // channel group
    int sub = lane >> 4;        // which edge of the pair
    int h = l >> 3;             // head

    int gw = (((blockIdx.x >> 1) * blockDim.x) + tid) >> 5;   // warp id in relation
    int nw = ((gridDim.x >> 1) * blockDim.x) >> 5;

    // a_attn slice for this lane's 4 channels (eb part, offset 96)
    float4 ae = __ldg(reinterpret_cast<const float4*>(a_attn + 96) + (l & 7));
    // per-head relation constant
    float4 r4 = __ldg(reinterpret_cast<const float4*>(relv) + l);
    float cc = tanh_h(r4.x) * ae.x + tanh_h(r4.y) * ae.y
             + tanh_h(r4.z) * ae.z + tanh_h(r4.w) * ae.w;
    cc += __shfl_xor_sync(0xffffffffu, cc, 4);
    cc += __shfl_xor_sync(0xffffffffu, cc, 2);
    cc += __shfl_xor_sync(0xffffffffu, cc, 1);

    for (int ep = gw; ep < EE / 2; ep += nw) {
        int e = ep * 2 + sub;
        int r = __ldg(row + e);
        int c = __ldg(col + e);

        const float4* eap = reinterpret_cast<const float4*>(ea + (size_t)e * 16);
        float4 A = __ldg(eap), B = __ldg(eap + 1), C4 = __ldg(eap + 2), D = __ldg(eap + 3);
        float eav[16] = {A.x, A.y, A.z, A.w, B.x, B.y, B.z, B.w,
                         C4.x, C4.y, C4.z, C4.w, D.x, D.y, D.z, D.w};

        float4 eb = make_float4(0.f, 0.f, 0.f, 0.f);
#pragma unroll
        for (int k = 0; k < 16; k++) {
            float4 w = sWe[k * 16 + l];
            eb.x = fmaf(eav[k], w.x, eb.x);
            eb.y = fmaf(eav[k], w.y, eb.y);
            eb.z = fmaf(eav[k], w.z, eb.z);
            eb.w = fmaf(eav[k], w.w, eb.w);
        }

        float se = tanh_h(eb.x) * ae.x + tanh_h(eb.y) * ae.y
                 + tanh_h(eb.z) * ae.z + tanh_h(eb.w) * ae.w;
        se += __shfl_xor_sync(0xffffffffu, se, 4);
        se += __shfl_xor_sync(0xffffffffu, se, 2);
        se += __shfl_xor_sync(0xffffffffu, se, 1);

        float score = se + cc + __ldg(SQd + 2 * c + h) + __ldg(SKs + 2 * r + h);
        float ex = __expf(score);

        float4 v4 = __ldg(reinterpret_cast<const float4*>(vps + r * 64) + l);
        float4 m;
        m.x = (v4.x + eb.x) * ex;
        m.y = (v4.y + eb.y) * ex;
        m.z = (v4.z + eb.z) * ex;
        m.w = (v4.w + eb.w) * ex;

        red_add_v4(agg + c * 64 + 4 * l, m);
        if ((l & 7) == 0) atomicAdd(s + 2 * c + h, ex);
    }
}

// ---------------- epilogue: fin = (agg/s)@Wo + bo + x@Wr (both types) ------
__global__ void __launch_bounds__(128) final_kernel(
    const float* __restrict__ agg_a, const float* __restrict__ s_a,
    const float* __restrict__ x_a,
    const float* __restrict__ Wo_a, const float* __restrict__ bo_a,
    const float* __restrict__ Wr_a,
    const float* __restrict__ agg_b, const float* __restrict__ s_b,
    const float* __restrict__ x_b,
    const float* __restrict__ Wo_b, const float* __restrict__ bo_b,
    const float* __restrict__ Wr_b,
    float* __restrict__ out, int pb)
{
    int typ = (blockIdx.x >= pb);
    int blk = typ ? (blockIdx.x - pb) : blockIdx.x;
    const float* agg = typ ? agg_b : agg_a;
    const float* s   = typ ? s_b   : s_a;
    const float* x   = typ ? x_b   : x_a;
    const float* Wo  = typ ? Wo_b  : Wo_a;
    const float* bo  = typ ? bo_b  : bo_a;
    const float* Wr  = typ ? Wr_b  : Wr_a;
    float* outp = out + (typ ? NN * 32 : 0);

    __shared__ float sWo[64 * 32];
    __shared__ float sWr[64 * 32];
    __shared__ float sbo[32];
    int tid = threadIdx.x;
    for (int i = tid; i < 2048; i += 128) { sWo[i] = Wo[i]; sWr[i] = Wr[i]; }
    if (tid < 32) sbo[tid] = bo[tid];
    __syncthreads();

    int node = blk * 128 + tid;
    if (node >= NN) return;

    float s0 = __ldg(s + node * 2);
    float s1 = __ldg(s + node * 2 + 1);
    float i0 = (s0 != 0.f) ? __fdividef(1.f, s0) : 0.f;
    float i1 = (s1 != 0.f) ? __fdividef(1.f, s1) : 0.f;

    float an[64], xr[64];
    const float4* ap = reinterpret_cast<const float4*>(agg + node * 64);
    const float4* xp = reinterpret_cast<const float4*>(x + node * 64);
#pragma unroll
    for (int i = 0; i < 16; i++) {
        float inv = (i < 8) ? i0 : i1;
        float4 a4 = __ldg(ap + i);
        an[i * 4 + 0] = a4.x * inv; an[i * 4 + 1] = a4.y * inv;
        an[i * 4 + 2] = a4.z * inv; an[i * 4 + 3] = a4.w * inv;
        float4 x4 = __ldg(xp + i);
        xr[i * 4 + 0] = x4.x; xr[i * 4 + 1] = x4.y;
        xr[i * 4 + 2] = x4.z; xr[i * 4 + 3] = x4.w;
    }

    float* op = outp + node * 32;
#pragma unroll 1
    for (int jc = 0; jc < 8; jc++) {
        int j4 = jc * 4;
        float4 acc = *reinterpret_cast<const float4*>(sbo + j4);
#pragma unroll
        for (int kk = 0; kk < 64; kk++) {
            float4 wo4 = *reinterpret_cast<const float4*>(sWo + kk * 32 + j4);
            float4 wr4 = *reinterpret_cast<const float4*>(sWr + kk * 32 + j4);
            float av = an[kk], xv = xr[kk];
            acc.x = fmaf(av, wo4.x, acc.x); acc.y = fmaf(av, wo4.y, acc.y);
            acc.z = fmaf(av, wo4.z, acc.z); acc.w = fmaf(av, wo4.w, acc.w);
            acc.x = fmaf(xv, wr4.x, acc.x); acc.y = fmaf(xv, wr4.y, acc.y);
            acc.z = fmaf(xv, wr4.z, acc.z); acc.w = fmaf(xv, wr4.w, acc.w);
        }
        *reinterpret_cast<float4*>(op + j4) = acc;
    }
}

// ---------------- launch ---------------------------------------------------
extern "C" void kernel_launch(void* const* d_in, const int* in_sizes, int n_in,
                              void* d_out, int out_size) {
    const float* x_a   = (const float*)d_in[0];
    const float* x_b   = (const float*)d_in[1];
    const float* ea1   = (const float*)d_in[2];
    const float* ea2   = (const float*)d_in[3];
    const float* Wq_a  = (const float*)d_in[4];
    const float* Wk_a  = (const float*)d_in[5];
    const float* Wv_a  = (const float*)d_in[6];
    const float* Wq_b  = (const float*)d_in[7];
    const float* Wk_b  = (const float*)d_in[8];
    const float* Wv_b  = (const float*)d_in[9];
    const float* emb_a = (const float*)d_in[10];
    const float* emb_b = (const float*)d_in[11];
    const float* rel1  = (const float*)d_in[12];
    const float* rel2  = (const float*)d_in[13];
    const float* We    = (const float*)d_in[14];
    const float* a_at  = (const float*)d_in[15];
    const float* Wo_a  = (const float*)d_in[16];
    const float* bo_a  = (const float*)d_in[17];
    const float* Wo_b  = (const float*)d_in[18];
    const float* bo_b  = (const float*)d_in[19];
    const float* Wr_a  = (const float*)d_in[20];
    const float* Wr_b  = (const float*)d_in[21];
    const int*   row1  = (const int*)d_in[22];
    const int*   col1  = (const int*)d_in[23];
    const int*   row2  = (const int*)d_in[24];
    const int*   col2  = (const int*)d_in[25];
    float* out = (float*)d_out;

    void *pSQa, *pSKa, *pSQb, *pSKb, *pvpa, *pvpb, *psa, *psb, *pagga, *paggb;
    cudaGetSymbolAddress(&pSQa, g_SQa);
    cudaGetSymbolAddress(&pSKa, g_SKa);
    cudaGetSymbolAddress(&pSQb, g_SQb);
    cudaGetSymbolAddress(&pSKb, g_SKb);
    cudaGetSymbolAddress(&pvpa, g_vpa);
    cudaGetSymbolAddress(&pvpb, g_vpb);
    cudaGetSymbolAddress(&psa, g_sa);
    cudaGetSymbolAddress(&psb, g_sb);
    cudaGetSymbolAddress(&pagga, g_agga);
    cudaGetSymbolAddress(&paggb, g_aggb);

    zero_all_kernel<<<(NN * 16 + 255) / 256, 256>>>();

    int pblocks = (NN + 127) / 128;
    // type a uses (emb_a, rel1): it is source in relation1.
    // type b uses (emb_b, rel2): it is source in relation2.
    proj_kernel<<<2 * pblocks, 128>>>(
        x_a, Wq_a, Wk_a, Wv_a, emb_a, rel1,
        (float*)pSQa, (float*)pSKa, (float*)pvpa,
        x_b, Wq_b, Wk_b, Wv_b, emb_b, rel2,
        (float*)pSQb, (float*)pSKb, (float*)pvpb,
        a_at, pblocks);

    // relation1 (even blocks): a -> b (dst=b); relation2 (odd blocks): b -> a.
    edge_kernel<<<4096, 256>>>(
        ea1, row1, col1, (const float*)pSQb, (const float*)pSKa,
        (const float*)pvpa, (float*)psb, (float*)paggb, rel1,
        ea2, row2, col2, (const float*)pSQa, (const float*)pSKb,
        (const float*)pvpb, (float*)psa, (float*)pagga, rel2,
        a_at, We);

    final_kernel<<<2 * pblocks, 128>>>(
        (const float*)pagga, (const float*)psa, x_a, Wo_a, bo_a, Wr_a,
        (const float*)paggb, (const float*)psb, x_b, Wo_b, bo_b, Wr_b,
        out, pblocks);
}